// round 2
// baseline (speedup 1.0000x reference)
#include <cuda_runtime.h>
#include <math.h>

#define N_NODES_MAX 100000
#define NODE_DIM    128
#define HIDDEN      64

// Scratch (no allocations allowed -> __device__ globals)
__device__ float g_emb [N_NODES_MAX * HIDDEN];   // relu(X @ W_enc + b)
__device__ float g_msg [N_NODES_MAX * HIDDEN];   // segment-sum of g_emb[src] into dst
__device__ float g_emb2[N_NODES_MAX * HIDDEN];   // relu((emb+msg) @ W_conv + b)

// ---------------------------------------------------------------------------
// Kernel 1: encode  emb = relu(X @ W_enc + b_enc), and zero g_msg rows.
// One thread per node, 64 accumulators in registers, W_enc in shared.
// ---------------------------------------------------------------------------
__global__ __launch_bounds__(256)
void encode_kernel(const float* __restrict__ X,
                   const float* __restrict__ W,   // [128,64]
                   const float* __restrict__ b,   // [64]
                   int n_nodes)
{
    __shared__ float sW[NODE_DIM * HIDDEN];  // 32 KB
    __shared__ float sb[HIDDEN];
    for (int i = threadIdx.x; i < NODE_DIM * HIDDEN; i += blockDim.x) sW[i] = W[i];
    if (threadIdx.x < HIDDEN) sb[threadIdx.x] = b[threadIdx.x];
    __syncthreads();

    int node = blockIdx.x * blockDim.x + threadIdx.x;
    if (node >= n_nodes) return;

    float acc[HIDDEN];
#pragma unroll
    for (int h = 0; h < HIDDEN; h++) acc[h] = sb[h];

    const float4* xrow = (const float4*)(X + (size_t)node * NODE_DIM);
    for (int k4 = 0; k4 < NODE_DIM / 4; k4++) {
        float4 x = __ldg(xrow + k4);
        const float* w0 = &sW[(4 * k4 + 0) * HIDDEN];
        const float* w1 = &sW[(4 * k4 + 1) * HIDDEN];
        const float* w2 = &sW[(4 * k4 + 2) * HIDDEN];
        const float* w3 = &sW[(4 * k4 + 3) * HIDDEN];
#pragma unroll
        for (int h4 = 0; h4 < HIDDEN / 4; h4++) {
            float4 a0 = *(const float4*)(w0 + 4 * h4);
            float4 a1 = *(const float4*)(w1 + 4 * h4);
            float4 a2 = *(const float4*)(w2 + 4 * h4);
            float4 a3 = *(const float4*)(w3 + 4 * h4);
            acc[4*h4+0] += x.x*a0.x + x.y*a1.x + x.z*a2.x + x.w*a3.x;
            acc[4*h4+1] += x.x*a0.y + x.y*a1.y + x.z*a2.y + x.w*a3.y;
            acc[4*h4+2] += x.x*a0.z + x.y*a1.z + x.z*a2.z + x.w*a3.z;
            acc[4*h4+3] += x.x*a0.w + x.y*a1.w + x.z*a2.w + x.w*a3.w;
        }
    }

    float4* er = (float4*)(g_emb + (size_t)node * HIDDEN);
    float4* mr = (float4*)(g_msg + (size_t)node * HIDDEN);
    float4 z4 = make_float4(0.f, 0.f, 0.f, 0.f);
#pragma unroll
    for (int h4 = 0; h4 < HIDDEN / 4; h4++) {
        float4 v;
        v.x = fmaxf(acc[4*h4+0], 0.f);
        v.y = fmaxf(acc[4*h4+1], 0.f);
        v.z = fmaxf(acc[4*h4+2], 0.f);
        v.w = fmaxf(acc[4*h4+3], 0.f);
        er[h4] = v;
        mr[h4] = z4;   // zero messages for the scatter phase
    }
}

// ---------------------------------------------------------------------------
// Kernel 2: edge scatter-add.  16 threads per edge, each moves one float4 via
// vector reduction (red.global.add.v4.f32, sm_90+). emb/msg live in L2.
// ---------------------------------------------------------------------------
__global__ __launch_bounds__(256)
void edge_kernel(const int* __restrict__ ei, int n_edges)
{
    long long t = (long long)blockIdx.x * blockDim.x + threadIdx.x;
    int e = (int)(t >> 4);
    int c = (int)(t & 15);
    if (e >= n_edges) return;

    int src = ei[e];
    int dst = ei[n_edges + e];

    float4 v = *(const float4*)(g_emb + (size_t)src * HIDDEN + c * 4);
    float* p = g_msg + (size_t)dst * HIDDEN + c * 4;
    asm volatile("red.global.add.v4.f32 [%0], {%1, %2, %3, %4};"
                 :: "l"(p), "f"(v.x), "f"(v.y), "f"(v.z), "f"(v.w)
                 : "memory");
}

// ---------------------------------------------------------------------------
// Kernel 3: conv  emb2 = relu((emb + msg) @ W_conv + b_conv)
// ---------------------------------------------------------------------------
__global__ __launch_bounds__(256)
void conv_kernel(const float* __restrict__ W,   // [64,64]
                 const float* __restrict__ b,   // [64]
                 int n_nodes)
{
    __shared__ float sW[HIDDEN * HIDDEN];  // 16 KB
    __shared__ float sb[HIDDEN];
    for (int i = threadIdx.x; i < HIDDEN * HIDDEN; i += blockDim.x) sW[i] = W[i];
    if (threadIdx.x < HIDDEN) sb[threadIdx.x] = b[threadIdx.x];
    __syncthreads();

    int node = blockIdx.x * blockDim.x + threadIdx.x;
    if (node >= n_nodes) return;

    float acc[HIDDEN];
#pragma unroll
    for (int h = 0; h < HIDDEN; h++) acc[h] = sb[h];

    const float4* er = (const float4*)(g_emb + (size_t)node * HIDDEN);
    const float4* mr = (const float4*)(g_msg + (size_t)node * HIDDEN);
    for (int k4 = 0; k4 < HIDDEN / 4; k4++) {
        float4 e = er[k4];
        float4 m = mr[k4];
        float4 x;
        x.x = e.x + m.x; x.y = e.y + m.y; x.z = e.z + m.z; x.w = e.w + m.w;
        const float* w0 = &sW[(4 * k4 + 0) * HIDDEN];
        const float* w1 = &sW[(4 * k4 + 1) * HIDDEN];
        const float* w2 = &sW[(4 * k4 + 2) * HIDDEN];
        const float* w3 = &sW[(4 * k4 + 3) * HIDDEN];
#pragma unroll
        for (int h4 = 0; h4 < HIDDEN / 4; h4++) {
            float4 a0 = *(const float4*)(w0 + 4 * h4);
            float4 a1 = *(const float4*)(w1 + 4 * h4);
            float4 a2 = *(const float4*)(w2 + 4 * h4);
            float4 a3 = *(const float4*)(w3 + 4 * h4);
            acc[4*h4+0] += x.x*a0.x + x.y*a1.x + x.z*a2.x + x.w*a3.x;
            acc[4*h4+1] += x.x*a0.y + x.y*a1.y + x.z*a2.y + x.w*a3.y;
            acc[4*h4+2] += x.x*a0.z + x.y*a1.z + x.z*a2.z + x.w*a3.z;
            acc[4*h4+3] += x.x*a0.w + x.y*a1.w + x.z*a2.w + x.w*a3.w;
        }
    }

    float4* o = (float4*)(g_emb2 + (size_t)node * HIDDEN);
#pragma unroll
    for (int h4 = 0; h4 < HIDDEN / 4; h4++) {
        float4 v;
        v.x = fmaxf(acc[4*h4+0], 0.f);
        v.y = fmaxf(acc[4*h4+1], 0.f);
        v.z = fmaxf(acc[4*h4+2], 0.f);
        v.w = fmaxf(acc[4*h4+3], 0.f);
        o[h4] = v;
    }
}

// ---------------------------------------------------------------------------
// Kernel 4: posts  out[p] = sigmoid(dot(emb2[mask[p]], W_out) + b_out)
// ---------------------------------------------------------------------------
__global__ __launch_bounds__(256)
void post_kernel(const int* __restrict__ mask,
                 const float* __restrict__ Wout,  // [64,1]
                 const float* __restrict__ bout,  // [1]
                 float* __restrict__ out,
                 int n_posts)
{
    __shared__ float sw[HIDDEN];
    if (threadIdx.x < HIDDEN) sw[threadIdx.x] = Wout[threadIdx.x];
    __syncthreads();

    int p = blockIdx.x * blockDim.x + threadIdx.x;
    if (p >= n_posts) return;

    int node = mask[p];
    const float4* r = (const float4*)(g_emb2 + (size_t)node * HIDDEN);
    float s = __ldg(bout);
#pragma unroll
    for (int k4 = 0; k4 < HIDDEN / 4; k4++) {
        float4 v = r[k4];
        const float4 w = *(const float4*)(sw + 4 * k4);
        s += v.x * w.x + v.y * w.y + v.z * w.z + v.w * w.w;
    }
    out[p] = 1.0f / (1.0f + expf(-s));
}

// ---------------------------------------------------------------------------
// Launch
// ---------------------------------------------------------------------------
extern "C" void kernel_launch(void* const* d_in, const int* in_sizes, int n_in,
                              void* d_out, int out_size)
{
    const float* node_features = (const float*)d_in[0];
    const int*   edge_index    = (const int*)d_in[1];
    const int*   post_mask     = (const int*)d_in[2];
    const float* W_enc         = (const float*)d_in[3];
    const float* b_enc         = (const float*)d_in[4];
    const float* W_conv        = (const float*)d_in[5];
    const float* b_conv        = (const float*)d_in[6];
    const float* W_out         = (const float*)d_in[7];
    const float* b_out         = (const float*)d_in[8];
    float*       out           = (float*)d_out;

    int n_nodes = in_sizes[0] / NODE_DIM;
    int n_edges = in_sizes[1] / 2;
    int n_posts = in_sizes[2];

    // 1. encode + zero msg
    {
        int threads = 256;
        int blocks = (n_nodes + threads - 1) / threads;
        encode_kernel<<<blocks, threads>>>(node_features, W_enc, b_enc, n_nodes);
    }
    // 2. edge scatter-add (16 threads / edge)
    {
        int threads = 256;
        long long total = (long long)n_edges * 16;
        int blocks = (int)((total + threads - 1) / threads);
        edge_kernel<<<blocks, threads>>>(edge_index, n_edges);
    }
    // 3. conv
    {
        int threads = 256;
        int blocks = (n_nodes + threads - 1) / threads;
        conv_kernel<<<blocks, threads>>>(W_conv, b_conv, n_nodes);
    }
    // 4. posts
    {
        int threads = 256;
        int blocks = (n_posts + threads - 1) / threads;
        post_kernel<<<blocks, threads>>>(post_mask, W_out, b_out, out, n_posts);
    }
}